// round 2
// baseline (speedup 1.0000x reference)
#include <cuda_runtime.h>
#include <math.h>

#define BATCH 4
#define SEQ   2048
#define DMOD  1024
#define HD    64
#define SCALE 0.125f

// scratch (static __device__ per harness rules): ~214 MB total
__device__ float g_P[6][BATCH*SEQ*HD];     // projections: Qu,Ku,Vu,Qc,Kc,Vc
__device__ float g_T1[BATCH][SEQ*SEQ];     // term1 (lower tri + 1 zero supradiag 64-tile)
__device__ float g_SG[BATCH][SEQ*SEQ];     // sigmoid gate (upper tri + 1 zero subdiag 64-tile)
__device__ float g_M [BATCH][SEQ*SEQ];     // softmax logits (lower tri tiles only)

// ---------------------------------------------------------------------------
// Projections: out[w][row,d] = X[row,:] @ W[w][:,d]; 64x64 tile, 4x4 microtile
// ---------------------------------------------------------------------------
__global__ __launch_bounds__(256) void proj_kernel(
    const float* __restrict__ x,
    const float* __restrict__ w0, const float* __restrict__ w1,
    const float* __restrict__ w2, const float* __restrict__ w3,
    const float* __restrict__ w4, const float* __restrict__ w5)
{
    __shared__ float Xs[64][17];
    __shared__ float Ws[16][64];
    const int wi = blockIdx.y;
    const float* w = w0;
    if (wi==1) w=w1; else if (wi==2) w=w2; else if (wi==3) w=w3;
    else if (wi==4) w=w4; else if (wi==5) w=w5;

    const int tid = threadIdx.x;
    const int tx = tid & 15, ty = tid >> 4;
    const int i0 = blockIdx.x * 64;
    const int xr = tid >> 2,  xc = (tid & 3)  << 2;   // X tile 64x16
    const int wr = tid >> 4,  wc = (tid & 15) << 2;   // W tile 16x64

    float acc[4][4] = {};
    for (int k0 = 0; k0 < DMOD; k0 += 16) {
        float4 xv = *(const float4*)(x + (size_t)(i0+xr)*DMOD + k0 + xc);
        float4 wv = *(const float4*)(w + (size_t)(k0+wr)*HD  + wc);
        __syncthreads();
        Xs[xr][xc+0]=xv.x; Xs[xr][xc+1]=xv.y; Xs[xr][xc+2]=xv.z; Xs[xr][xc+3]=xv.w;
        *(float4*)&Ws[wr][wc] = wv;
        __syncthreads();
        #pragma unroll
        for (int kk=0; kk<16; kk++) {
            float af[4], bf[4];
            #pragma unroll
            for (int u=0;u<4;u++) af[u]=Xs[ty*4+u][kk];
            #pragma unroll
            for (int v=0;v<4;v++) bf[v]=Ws[kk][tx*4+v];
            #pragma unroll
            for (int u=0;u<4;u++)
                #pragma unroll
                for (int v=0;v<4;v++) acc[u][v] = fmaf(af[u], bf[v], acc[u][v]);
        }
    }
    float* out = g_P[wi];
    #pragma unroll
    for (int u=0;u<4;u++) {
        int row = i0 + ty*4 + u;
        *(float4*)(out + (size_t)row*HD + tx*4) =
            make_float4(acc[u][0],acc[u][1],acc[u][2],acc[u][3]);
    }
}

// ---------------------------------------------------------------------------
// term1 (which=0): Qc . Vu^T * scale, masked j<=i  (tiles jt <= rt+1)
// sigma (which=1): sigmoid(Qu . Ku^T * scale) masked j>k (tiles jt >= rt-1)
// 64x64 tile, K=64 (=DH)
// ---------------------------------------------------------------------------
__global__ __launch_bounds__(256) void ts_kernel()
{
    const int jt = blockIdx.x, rt = blockIdx.y;
    const int which = blockIdx.z & 1, b = blockIdx.z >> 1;
    if (which == 0) { if (jt > rt + 1) return; }
    else            { if (jt + 1 < rt) return; }

    const int tid = threadIdx.x;
    const int tx = tid & 15, ty = tid >> 4;
    const int r0 = rt * 64, j0 = jt * 64;
    float* outp = which ? g_SG[b] : g_T1[b];

    const bool zero_tile = which ? (jt + 1 == rt) : (jt == rt + 1);
    if (zero_tile) {
        float4 z = make_float4(0.f,0.f,0.f,0.f);
        #pragma unroll
        for (int s=0;s<4;s++) {
            int r = (tid>>4) + 16*s, c = (tid&15)<<2;
            *(float4*)(outp + (size_t)(r0+r)*SEQ + j0 + c) = z;
        }
        return;
    }

    const float* A  = (which ? g_P[0] : g_P[3]) + (size_t)b*SEQ*HD;
    const float* Bm = (which ? g_P[1] : g_P[2]) + (size_t)b*SEQ*HD;

    __shared__ float As[64][65], Bs[64][65];
    #pragma unroll
    for (int s=0;s<4;s++) {
        int r = (tid>>4) + 16*s, c = (tid&15)<<2;
        float4 av = *(const float4*)(A  + (size_t)(r0+r)*HD + c);
        float4 bv = *(const float4*)(Bm + (size_t)(j0+r)*HD + c);
        As[r][c+0]=av.x; As[r][c+1]=av.y; As[r][c+2]=av.z; As[r][c+3]=av.w;
        Bs[r][c+0]=bv.x; Bs[r][c+1]=bv.y; Bs[r][c+2]=bv.z; Bs[r][c+3]=bv.w;
    }
    __syncthreads();

    float acc[4][4] = {};
    #pragma unroll 8
    for (int d=0; d<64; d++) {
        float af[4], bf[4];
        #pragma unroll
        for (int u=0;u<4;u++) af[u]=As[ty*4+u][d];
        #pragma unroll
        for (int v=0;v<4;v++) bf[v]=Bs[tx*4+v][d];
        #pragma unroll
        for (int u=0;u<4;u++)
            #pragma unroll
            for (int v=0;v<4;v++) acc[u][v] = fmaf(af[u], bf[v], acc[u][v]);
    }

    #pragma unroll
    for (int u=0;u<4;u++) {
        int r = r0 + ty*4 + u;
        float vals[4];
        #pragma unroll
        for (int v=0;v<4;v++) {
            int j = j0 + tx*4 + v;
            float val = acc[u][v]*SCALE;
            if (which == 0) { if (j > r) val = 0.f; }
            else            { val = (j > r) ? 1.f/(1.f + __expf(-val)) : 0.f; }
            vals[v] = val;
        }
        *(float4*)(outp + (size_t)r*SEQ + j0 + tx*4) =
            make_float4(vals[0],vals[1],vals[2],vals[3]);
    }
}

// ---------------------------------------------------------------------------
// S_u + S_c fusion: M[i,k] = (k<=i) ? Qc.Kc*scale - silu(S_u) : -1e30
// S_u tile = term1[i, j] . sigma[k, j]^T over j in (k0, i0+128]
// 128x128 tile, 8x8 microtile, triangular grid ordered largest-work-first
// ---------------------------------------------------------------------------
__global__ __launch_bounds__(256) void su_kernel()
{
    int rem = blockIdx.x;
    int dd = 15;
    while (rem >= 16 - dd) { rem -= 16 - dd; dd--; }
    const int kt = rem, it = kt + dd;
    const int b = blockIdx.y;
    const int i0 = it*128, k0 = kt*128;

    const int tid = threadIdx.x;
    const int tx = tid & 15, ty = tid >> 4;

    __shared__ float As[128][17];
    __shared__ float Bs[128][17];

    const float* T1 = g_T1[b];
    const float* SG = g_SG[b];

    float acc[8][8] = {};
    const int lr = tid >> 2, lc = (tid & 3) << 2;   // 128x16 tile loads

    for (int j = k0; j < i0 + 128; j += 16) {
        float4 a0 = *(const float4*)(T1 + (size_t)(i0+lr   )*SEQ + j + lc);
        float4 a1 = *(const float4*)(T1 + (size_t)(i0+lr+64)*SEQ + j + lc);
        float4 c0 = *(const float4*)(SG + (size_t)(k0+lr   )*SEQ + j + lc);
        float4 c1 = *(const float4*)(SG + (size_t)(k0+lr+64)*SEQ + j + lc);
        __syncthreads();
        As[lr   ][lc+0]=a0.x; As[lr   ][lc+1]=a0.y; As[lr   ][lc+2]=a0.z; As[lr   ][lc+3]=a0.w;
        As[lr+64][lc+0]=a1.x; As[lr+64][lc+1]=a1.y; As[lr+64][lc+2]=a1.z; As[lr+64][lc+3]=a1.w;
        Bs[lr   ][lc+0]=c0.x; Bs[lr   ][lc+1]=c0.y; Bs[lr   ][lc+2]=c0.z; Bs[lr   ][lc+3]=c0.w;
        Bs[lr+64][lc+0]=c1.x; Bs[lr+64][lc+1]=c1.y; Bs[lr+64][lc+2]=c1.z; Bs[lr+64][lc+3]=c1.w;
        __syncthreads();
        #pragma unroll
        for (int jj=0; jj<16; jj++) {
            float af[8], bf[8];
            #pragma unroll
            for (int u=0;u<8;u++) af[u] = As[ty*8+u][jj];
            #pragma unroll
            for (int v=0;v<8;v++) bf[v] = Bs[tx*8+v][jj];
            #pragma unroll
            for (int u=0;u<8;u++)
                #pragma unroll
                for (int v=0;v<8;v++) acc[u][v] = fmaf(af[u], bf[v], acc[u][v]);
        }
    }

    // acc := -silu(S_u)
    #pragma unroll
    for (int u=0;u<8;u++)
        #pragma unroll
        for (int v=0;v<8;v++) {
            float s_ = acc[u][v];
            acc[u][v] = -(s_ / (1.f + __expf(-s_)));
        }

    // acc += scale * Qc . Kc^T  (K=64 in 4 chunks of 16, reusing smem)
    const float* Qc = g_P[3] + (size_t)b*SEQ*HD;
    const float* Kc = g_P[4] + (size_t)b*SEQ*HD;
    for (int dc = 0; dc < 64; dc += 16) {
        float4 a0 = *(const float4*)(Qc + (size_t)(i0+lr   )*HD + dc + lc);
        float4 a1 = *(const float4*)(Qc + (size_t)(i0+lr+64)*HD + dc + lc);
        float4 c0 = *(const float4*)(Kc + (size_t)(k0+lr   )*HD + dc + lc);
        float4 c1 = *(const float4*)(Kc + (size_t)(k0+lr+64)*HD + dc + lc);
        __syncthreads();
        As[lr   ][lc+0]=a0.x; As[lr   ][lc+1]=a0.y; As[lr   ][lc+2]=a0.z; As[lr   ][lc+3]=a0.w;
        As[lr+64][lc+0]=a1.x; As[lr+64][lc+1]=a1.y; As[lr+64][lc+2]=a1.z; As[lr+64][lc+3]=a1.w;
        Bs[lr   ][lc+0]=c0.x; Bs[lr   ][lc+1]=c0.y; Bs[lr   ][lc+2]=c0.z; Bs[lr   ][lc+3]=c0.w;
        Bs[lr+64][lc+0]=c1.x; Bs[lr+64][lc+1]=c1.y; Bs[lr+64][lc+2]=c1.z; Bs[lr+64][lc+3]=c1.w;
        __syncthreads();
        #pragma unroll
        for (int jj=0; jj<16; jj++) {
            float af[8], bf[8];
            #pragma unroll
            for (int u=0;u<8;u++) af[u] = SCALE * As[ty*8+u][jj];
            #pragma unroll
            for (int v=0;v<8;v++) bf[v] = Bs[tx*8+v][jj];
            #pragma unroll
            for (int u=0;u<8;u++)
                #pragma unroll
                for (int v=0;v<8;v++) acc[u][v] = fmaf(af[u], bf[v], acc[u][v]);
        }
    }

    float* M = g_M[b];
    #pragma unroll
    for (int u=0;u<8;u++) {
        int i = i0 + ty*8 + u;
        float o[8];
        #pragma unroll
        for (int v=0;v<8;v++) {
            int k = k0 + tx*8 + v;
            o[v] = (k <= i) ? acc[u][v] : -1e30f;
        }
        *(float4*)(M + (size_t)i*SEQ + k0 + tx*8    ) = make_float4(o[0],o[1],o[2],o[3]);
        *(float4*)(M + (size_t)i*SEQ + k0 + tx*8 + 4) = make_float4(o[4],o[5],o[6],o[7]);
    }
}

// ---------------------------------------------------------------------------
// Row softmax of M (over k <= i only) fused with @ V_c, flash-style online.
// 64-row block, k-tiles of 64, kt <= it.
// ---------------------------------------------------------------------------
__global__ __launch_bounds__(256) void softpv_kernel(float* __restrict__ out)
{
    const int it = 31 - blockIdx.x;     // largest work first
    const int b = blockIdx.y;
    const int i0 = it*64;
    const int tid = threadIdx.x;
    const int tx = tid & 15, ty = tid >> 4;

    __shared__ float Ms[64][65];
    __shared__ float Vs[64][65];

    const float* M  = g_M[b];
    const float* Vc = g_P[5] + (size_t)b*SEQ*HD;

    float acc[4][4] = {};
    float mrow[4], lrow[4];
    #pragma unroll
    for (int u=0;u<4;u++){ mrow[u] = -INFINITY; lrow[u] = 0.f; }

    for (int kt = 0; kt <= it; kt++) {
        const int k0 = kt*64;
        #pragma unroll
        for (int s=0;s<4;s++) {
            int r = (tid>>4) + 16*s, c = (tid&15)<<2;
            float4 mv = *(const float4*)(M  + (size_t)(i0+r)*SEQ + k0 + c);
            float4 vv = *(const float4*)(Vc + (size_t)(k0+r)*HD  + c);
            Ms[r][c+0]=mv.x; Ms[r][c+1]=mv.y; Ms[r][c+2]=mv.z; Ms[r][c+3]=mv.w;
            Vs[r][c+0]=vv.x; Vs[r][c+1]=vv.y; Vs[r][c+2]=vv.z; Vs[r][c+3]=vv.w;
        }
        __syncthreads();

        #pragma unroll
        for (int u=0;u<4;u++) {
            float tmax = -INFINITY;
            #pragma unroll
            for (int v=0;v<4;v++) tmax = fmaxf(tmax, Ms[ty*4+u][tx*4+v]);
            #pragma unroll
            for (int off=1; off<16; off<<=1)
                tmax = fmaxf(tmax, __shfl_xor_sync(0xffffffffu, tmax, off));
            float newm = fmaxf(mrow[u], tmax);
            float corr = __expf(mrow[u] - newm);
            mrow[u] = newm;
            float tsum = 0.f;
            #pragma unroll
            for (int v=0;v<4;v++) {
                float p = __expf(Ms[ty*4+u][tx*4+v] - newm);
                Ms[ty*4+u][tx*4+v] = p;
                tsum += p;
            }
            #pragma unroll
            for (int off=1; off<16; off<<=1)
                tsum += __shfl_xor_sync(0xffffffffu, tsum, off);
            lrow[u] = lrow[u]*corr + tsum;
            #pragma unroll
            for (int v=0;v<4;v++) acc[u][v] *= corr;
        }
        __syncthreads();

        #pragma unroll 8
        for (int kk=0; kk<64; kk++) {
            float af[4], bf[4];
            #pragma unroll
            for (int u=0;u<4;u++) af[u] = Ms[ty*4+u][kk];
            #pragma unroll
            for (int v=0;v<4;v++) bf[v] = Vs[kk][tx*4+v];
            #pragma unroll
            for (int u=0;u<4;u++)
                #pragma unroll
                for (int v=0;v<4;v++) acc[u][v] = fmaf(af[u], bf[v], acc[u][v]);
        }
        __syncthreads();
    }

    #pragma unroll
    for (int u=0;u<4;u++) {
        int row = i0 + ty*4 + u;
        float inv = 1.f / lrow[u];
        *(float4*)(out + ((size_t)b*SEQ + row)*HD + tx*4) =
            make_float4(acc[u][0]*inv, acc[u][1]*inv, acc[u][2]*inv, acc[u][3]*inv);
    }
}

// ---------------------------------------------------------------------------
extern "C" void kernel_launch(void* const* d_in, const int* in_sizes, int n_in,
                              void* d_out, int out_size)
{
    (void)in_sizes; (void)n_in; (void)out_size;
    const float* x    = (const float*)d_in[0];
    const float* wqu  = (const float*)d_in[1];
    const float* wku  = (const float*)d_in[2];
    const float* wvu  = (const float*)d_in[3];
    const float* wqc  = (const float*)d_in[4];
    const float* wkc  = (const float*)d_in[5];
    const float* wvc  = (const float*)d_in[6];
    float* out = (float*)d_out;

    proj_kernel<<<dim3(128, 6), 256>>>(x, wqu, wku, wvu, wqc, wkc, wvc);
    ts_kernel<<<dim3(32, 32, 8), 256>>>();
    su_kernel<<<dim3(136, 4), 256>>>();
    softpv_kernel<<<dim3(32, 4), 256>>>(out);
}

// round 17
// speedup vs baseline: 1.6063x; 1.6063x over previous
#include <cuda_runtime.h>
#include <cuda_bf16.h>
#include <math.h>
#include <stdint.h>

#define BATCH 4
#define SEQ   2048
#define DMOD  1024
#define HD    64
#define SCALE 0.125f

// ---------------- scratch (static __device__, no allocs) -------------------
__device__ __align__(256) float g_P[6][BATCH*SEQ*HD];          // Qu,Ku,Vu,Qc,Kc,Vc
__device__ __align__(256) __nv_bfloat16 g_T1h[BATCH][SEQ*SEQ]; // term1 hi
__device__ __align__(256) __nv_bfloat16 g_T1l[BATCH][SEQ*SEQ]; // term1 lo
__device__ __align__(256) __nv_bfloat16 g_SGh[BATCH][SEQ*SEQ]; // sigmoid gate hi
__device__ __align__(256) __nv_bfloat16 g_SGl[BATCH][SEQ*SEQ]; // sigmoid gate lo
__device__ __align__(256) __nv_bfloat16 g_Qch[BATCH*SEQ*HD];   // scale*Qc hi
__device__ __align__(256) __nv_bfloat16 g_Qcl[BATCH*SEQ*HD];   // scale*Qc lo
__device__ __align__(256) __nv_bfloat16 g_Kch[BATCH*SEQ*HD];   // Kc hi
__device__ __align__(256) __nv_bfloat16 g_Kcl[BATCH*SEQ*HD];   // Kc lo
__device__ __align__(256) float g_M[BATCH][SEQ*SEQ];           // logits (lower tri)

// ---------------- helpers (sm_80-class PTX only; NO tcgen05) ---------------
__device__ __forceinline__ uint32_t smem_u32(const void* p) {
    uint32_t a;
    asm("{ .reg .u64 t; cvta.to.shared.u64 t, %1; cvt.u32.u64 %0, t; }" : "=r"(a) : "l"(p));
    return a;
}
__device__ __forceinline__ uint32_t swz128(uint32_t b) { return b ^ ((b >> 3) & 0x70); }

#define STS128(addr, v) asm volatile("st.shared.v4.b32 [%0], {%1,%2,%3,%4};" :: "r"(addr), "r"((v).x), "r"((v).y), "r"((v).z), "r"((v).w) : "memory")

#define LDSM_X4(r, addr) \
    asm volatile("ldmatrix.sync.aligned.m8n8.x4.shared.b16 {%0,%1,%2,%3}, [%4];" \
        : "=r"((r)[0]), "=r"((r)[1]), "=r"((r)[2]), "=r"((r)[3]) : "r"(addr))

#define MMA16816(c, a, b0, b1) \
    asm volatile("mma.sync.aligned.m16n8k16.row.col.f32.bf16.bf16.f32 " \
        "{%0,%1,%2,%3}, {%4,%5,%6,%7}, {%8,%9}, {%0,%1,%2,%3};" \
        : "+f"((c)[0]), "+f"((c)[1]), "+f"((c)[2]), "+f"((c)[3]) \
        : "r"((a)[0]), "r"((a)[1]), "r"((a)[2]), "r"((a)[3]), "r"(b0), "r"(b1))

// ---------------------------------------------------------------------------
// Projections (fp32 SIMT). For Qc (wi=3): also emit bf16 hi/lo of SCALE*Qc.
// For Kc (wi=4): also emit bf16 hi/lo of Kc.
// ---------------------------------------------------------------------------
__global__ __launch_bounds__(256) void proj_kernel(
    const float* __restrict__ x,
    const float* __restrict__ w0, const float* __restrict__ w1,
    const float* __restrict__ w2, const float* __restrict__ w3,
    const float* __restrict__ w4, const float* __restrict__ w5)
{
    __shared__ float Xs[64][17];
    __shared__ float Ws[16][64];
    const int wi = blockIdx.y;
    const float* w = w0;
    if (wi==1) w=w1; else if (wi==2) w=w2; else if (wi==3) w=w3;
    else if (wi==4) w=w4; else if (wi==5) w=w5;

    const int tid = threadIdx.x;
    const int tx = tid & 15, ty = tid >> 4;
    const int i0 = blockIdx.x * 64;
    const int xr = tid >> 2,  xc = (tid & 3)  << 2;
    const int wr = tid >> 4,  wc = (tid & 15) << 2;

    float acc[4][4] = {};
    for (int k0 = 0; k0 < DMOD; k0 += 16) {
        float4 xv = *(const float4*)(x + (size_t)(i0+xr)*DMOD + k0 + xc);
        float4 wv = *(const float4*)(w + (size_t)(k0+wr)*HD  + wc);
        __syncthreads();
        Xs[xr][xc+0]=xv.x; Xs[xr][xc+1]=xv.y; Xs[xr][xc+2]=xv.z; Xs[xr][xc+3]=xv.w;
        *(float4*)&Ws[wr][wc] = wv;   // Ws row stride = 64 floats = 256B, 16B-aligned
        __syncthreads();
        #pragma unroll
        for (int kk=0; kk<16; kk++) {
            float af[4], bf[4];
            #pragma unroll
            for (int u=0;u<4;u++) af[u]=Xs[ty*4+u][kk];
            #pragma unroll
            for (int v=0;v<4;v++) bf[v]=Ws[kk][tx*4+v];
            #pragma unroll
            for (int u=0;u<4;u++)
                #pragma unroll
                for (int v=0;v<4;v++) acc[u][v] = fmaf(af[u], bf[v], acc[u][v]);
        }
    }
    float* out = g_P[wi];
    #pragma unroll
    for (int u=0;u<4;u++) {
        int row = i0 + ty*4 + u;
        *(float4*)(out + (size_t)row*HD + tx*4) =
            make_float4(acc[u][0],acc[u][1],acc[u][2],acc[u][3]);
    }
    if (wi == 3 || wi == 4) {
        __nv_bfloat16* oh = (wi==3) ? g_Qch : g_Kch;
        __nv_bfloat16* ol = (wi==3) ? g_Qcl : g_Kcl;
        const float s = (wi==3) ? SCALE : 1.0f;
        #pragma unroll
        for (int u=0;u<4;u++) {
            int row = i0 + ty*4 + u;
            size_t off = (size_t)row*HD + tx*4;
            __nv_bfloat16 h[4], l[4];
            #pragma unroll
            for (int v=0;v<4;v++) {
                float val = acc[u][v] * s;
                h[v] = __float2bfloat16(val);
                l[v] = __float2bfloat16(val - __bfloat162float(h[v]));
            }
            __nv_bfloat162 hh0; hh0.x=h[0]; hh0.y=h[1];
            __nv_bfloat162 hh1; hh1.x=h[2]; hh1.y=h[3];
            __nv_bfloat162 ll0; ll0.x=l[0]; ll0.y=l[1];
            __nv_bfloat162 ll1; ll1.x=l[2]; ll1.y=l[3];
            *(__nv_bfloat162*)(oh + off    ) = hh0;
            *(__nv_bfloat162*)(oh + off + 2) = hh1;
            *(__nv_bfloat162*)(ol + off    ) = ll0;
            *(__nv_bfloat162*)(ol + off + 2) = ll1;
        }
    }
}

// ---------------------------------------------------------------------------
// term1 (which=0): SCALE * Qc . Vu^T, masked j<=i, written as bf16 hi/lo
// sigma (which=1): sigmoid(SCALE * Qu . Ku^T) masked j>k, written as bf16 hi/lo
// ---------------------------------------------------------------------------
__global__ __launch_bounds__(256) void ts_kernel()
{
    const int jt = blockIdx.x, rt = blockIdx.y;
    const int which = blockIdx.z & 1, b = blockIdx.z >> 1;
    if (which == 0) { if (jt > rt + 1) return; }
    else            { if (jt + 1 < rt) return; }

    const int tid = threadIdx.x;
    const int tx = tid & 15, ty = tid >> 4;
    const int r0 = rt * 64, j0 = jt * 64;
    __nv_bfloat16* oh = which ? g_SGh[b] : g_T1h[b];
    __nv_bfloat16* ol = which ? g_SGl[b] : g_T1l[b];

    const bool zero_tile = which ? (jt + 1 == rt) : (jt == rt + 1);
    if (zero_tile) {
        __nv_bfloat162 z; z.x = __float2bfloat16(0.f); z.y = z.x;
        #pragma unroll
        for (int s=0;s<4;s++) {
            int r = (tid>>4) + 16*s, c = (tid&15)<<2;
            size_t off = (size_t)(r0+r)*SEQ + j0 + c;
            *(__nv_bfloat162*)(oh+off) = z; *(__nv_bfloat162*)(oh+off+2) = z;
            *(__nv_bfloat162*)(ol+off) = z; *(__nv_bfloat162*)(ol+off+2) = z;
        }
        return;
    }

    const float* A  = (which ? g_P[0] : g_P[3]) + (size_t)b*SEQ*HD;
    const float* Bm = (which ? g_P[1] : g_P[2]) + (size_t)b*SEQ*HD;

    __shared__ float As[64][65], Bs[64][65];
    #pragma unroll
    for (int s=0;s<4;s++) {
        int r = (tid>>4) + 16*s, c = (tid&15)<<2;
        float4 av = *(const float4*)(A  + (size_t)(r0+r)*HD + c);
        float4 bv = *(const float4*)(Bm + (size_t)(j0+r)*HD + c);
        As[r][c+0]=av.x; As[r][c+1]=av.y; As[r][c+2]=av.z; As[r][c+3]=av.w;
        Bs[r][c+0]=bv.x; Bs[r][c+1]=bv.y; Bs[r][c+2]=bv.z; Bs[r][c+3]=bv.w;
    }
    __syncthreads();

    float acc[4][4] = {};
    #pragma unroll 8
    for (int d=0; d<64; d++) {
        float af[4], bf[4];
        #pragma unroll
        for (int u=0;u<4;u++) af[u]=As[ty*4+u][d];
        #pragma unroll
        for (int v=0;v<4;v++) bf[v]=Bs[tx*4+v][d];
        #pragma unroll
        for (int u=0;u<4;u++)
            #pragma unroll
            for (int v=0;v<4;v++) acc[u][v] = fmaf(af[u], bf[v], acc[u][v]);
    }

    #pragma unroll
    for (int u=0;u<4;u++) {
        int r = r0 + ty*4 + u;
        __nv_bfloat16 h[4], l[4];
        #pragma unroll
        for (int v=0;v<4;v++) {
            int j = j0 + tx*4 + v;
            float val = acc[u][v]*SCALE;
            if (which == 0) { if (j > r) val = 0.f; }
            else            { val = (j > r) ? 1.f/(1.f + __expf(-val)) : 0.f; }
            h[v] = __float2bfloat16(val);
            l[v] = __float2bfloat16(val - __bfloat162float(h[v]));
        }
        size_t off = (size_t)r*SEQ + j0 + tx*4;
        __nv_bfloat162 hh0; hh0.x=h[0]; hh0.y=h[1];
        __nv_bfloat162 hh1; hh1.x=h[2]; hh1.y=h[3];
        __nv_bfloat162 ll0; ll0.x=l[0]; ll0.y=l[1];
        __nv_bfloat162 ll1; ll1.x=l[2]; ll1.y=l[3];
        *(__nv_bfloat162*)(oh+off)   = hh0; *(__nv_bfloat162*)(oh+off+2) = hh1;
        *(__nv_bfloat162*)(ol+off)   = ll0; *(__nv_bfloat162*)(ol+off+2) = ll1;
    }
}

// ---------------------------------------------------------------------------
// su_mma: warp-level mma.sync bf16 hi/lo split GEMM (no tcgen05 on this build).
// Phase 0: acc = S_u[i,k] = sum_j T1[i,j]*SG[k,j],  j in [k0, i0+128)
// Then acc := -silu(acc).
// Phase 1: acc += scale*Qc[i,:] . Kc[k,:]   (accumulates QcKc on top)
// M[i,k] = (k<=i) ? acc : -1e30
// CTA: 128x128 tile, 8 warps (4 row-groups x 2 col-groups), warp tile 32x64.
// 3-way split per product: hh + hl + lh (ll dropped, ~1e-5 contribution).
// ---------------------------------------------------------------------------
#define SU_AH 0
#define SU_AL 16384
#define SU_BH 32768
#define SU_BL 49152
#define SU_SM_TOT 65536

__global__ __launch_bounds__(256, 1) void su_mma_kernel()
{
    extern __shared__ char smem[];
    const uint32_t sb = smem_u32(smem);
    const uint32_t sAh = sb + SU_AH, sAl = sb + SU_AL;
    const uint32_t sBh = sb + SU_BH, sBl = sb + SU_BL;

    const int tid = threadIdx.x, wid = tid >> 5, lane = tid & 31;
    const int wr = wid & 3, wc = wid >> 2;      // warp row/col group
    const int lrow = lane & 15, lch = lane >> 4; // ldmatrix addressing

    int rem = blockIdx.x;
    int dd = 15;
    while (rem >= 16 - dd) { rem -= 16 - dd; dd--; }
    const int kt = rem, it = kt + dd;
    const int b = blockIdx.y;
    const int i0 = it*128, k0 = kt*128;

    const int nsu = 2*dd + 2;

    float acc[2][8][4] = {};

    for (int ph = 0; ph < 2; ph++) {
        const __nv_bfloat16* Ah = ph ? (g_Qch + (size_t)b*SEQ*HD) : g_T1h[b];
        const __nv_bfloat16* Al = ph ? (g_Qcl + (size_t)b*SEQ*HD) : g_T1l[b];
        const __nv_bfloat16* Bh = ph ? (g_Kch + (size_t)b*SEQ*HD) : g_SGh[b];
        const __nv_bfloat16* Bl = ph ? (g_Kcl + (size_t)b*SEQ*HD) : g_SGl[b];
        const size_t rs = ph ? (size_t)HD : (size_t)SEQ;
        const int nc = ph ? 1 : nsu;

        for (int c = 0; c < nc; c++) {
            const int j = ph ? 0 : (k0 + c*64);
            // global -> regs (4 x 16B per thread per buffer)
            uint4 rAh[4], rAl[4], rBh[4], rBl[4];
            #pragma unroll
            for (int s = 0; s < 4; s++) {
                int idx = tid + 256*s;
                int row = idx >> 3, ch = idx & 7;
                size_t oA = (size_t)(i0+row)*rs + j + ch*8;
                size_t oB = (size_t)(k0+row)*rs + j + ch*8;
                rAh[s] = *(const uint4*)(Ah + oA);
                rAl[s] = *(const uint4*)(Al + oA);
                rBh[s] = *(const uint4*)(Bh + oB);
                rBl[s] = *(const uint4*)(Bl + oB);
            }
            __syncthreads();   // previous chunk's mma reads complete
            #pragma unroll
            for (int s = 0; s < 4; s++) {
                int idx = tid + 256*s;
                int row = idx >> 3, ch = idx & 7;
                uint32_t sw = swz128((uint32_t)(row*128 + ch*16));
                STS128(sAh + sw, rAh[s]);
                STS128(sAl + sw, rAl[s]);
                STS128(sBh + sw, rBh[s]);
                STS128(sBl + sw, rBl[s]);
            }
            __syncthreads();

            // mma over 4 k-steps of 16
            #pragma unroll
            for (int ks = 0; ks < 4; ks++) {
                uint32_t ah[2][4], al[2][4];
                #pragma unroll
                for (int mt = 0; mt < 2; mt++) {
                    uint32_t sw = swz128((uint32_t)((wr*32 + mt*16 + lrow)*128 + ks*32 + lch*16));
                    LDSM_X4(ah[mt], sAh + sw);
                    LDSM_X4(al[mt], sAl + sw);
                }
                #pragma unroll
                for (int ng = 0; ng < 4; ng++) {
                    uint32_t sw = swz128((uint32_t)((wc*64 + ng*16 + lrow)*128 + ks*32 + lch*16));
                    uint32_t th[4], tl[4];
                    LDSM_X4(th, sBh + sw);
                    LDSM_X4(tl, sBl + sw);
                    #pragma unroll
                    for (int mt = 0; mt < 2; mt++) {
                        MMA16816(acc[mt][ng*2  ], ah[mt], th[0], th[2]);   // hh
                        MMA16816(acc[mt][ng*2  ], ah[mt], tl[0], tl[2]);   // hl
                        MMA16816(acc[mt][ng*2  ], al[mt], th[0], th[2]);   // lh
                        MMA16816(acc[mt][ng*2+1], ah[mt], th[1], th[3]);
                        MMA16816(acc[mt][ng*2+1], ah[mt], tl[1], tl[3]);
                        MMA16816(acc[mt][ng*2+1], al[mt], th[1], th[3]);
                    }
                }
            }
        }

        if (ph == 0) {
            // acc := -silu(acc)
            #pragma unroll
            for (int mt = 0; mt < 2; mt++)
                #pragma unroll
                for (int nt = 0; nt < 8; nt++)
                    #pragma unroll
                    for (int q = 0; q < 4; q++) {
                        float s_ = acc[mt][nt][q];
                        acc[mt][nt][q] = -(s_ / (1.f + __expf(-s_)));
                    }
        }
    }

    // epilogue: mask + store
    float* M = g_M[b];
    const int r0l = lane >> 2, c0l = (lane & 3) * 2;
    #pragma unroll
    for (int mt = 0; mt < 2; mt++) {
        const int ia = i0 + wr*32 + mt*16 + r0l;
        const int ib = ia + 8;
        #pragma unroll
        for (int nt = 0; nt < 8; nt++) {
            const int kc = k0 + wc*64 + nt*8 + c0l;
            float v0 = (kc     <= ia) ? acc[mt][nt][0] : -1e30f;
            float v1 = (kc + 1 <= ia) ? acc[mt][nt][1] : -1e30f;
            float v2 = (kc     <= ib) ? acc[mt][nt][2] : -1e30f;
            float v3 = (kc + 1 <= ib) ? acc[mt][nt][3] : -1e30f;
            *(float2*)(M + (size_t)ia*SEQ + kc) = make_float2(v0, v1);
            *(float2*)(M + (size_t)ib*SEQ + kc) = make_float2(v2, v3);
        }
    }
}

// ---------------------------------------------------------------------------
// Row softmax of M (over k <= i) fused with @ V_c, flash-style online.
// 32-row block, k-tiles of 64. SCALAR smem stores (padded stride 65 floats =
// 260B is NOT float4-aligned — vector stores here caused the R12/R15 trap).
// ---------------------------------------------------------------------------
__global__ __launch_bounds__(256) void softpv_kernel(float* __restrict__ out)
{
    const int it = 63 - blockIdx.x;     // largest work first
    const int b = blockIdx.y;
    const int i0 = it*32;
    const int tid = threadIdx.x;
    const int tx = tid & 15, ty = tid >> 4;

    __shared__ float Ms[32][65];
    __shared__ float Vs[64][65];

    const float* M  = g_M[b];
    const float* Vc = g_P[5] + (size_t)b*SEQ*HD;

    float acc[2][4] = {};
    float mrow[2] = {-INFINITY, -INFINITY};
    float lrow[2] = {0.f, 0.f};

    const int ktmax = it >> 1;
    for (int kt = 0; kt <= ktmax; kt++) {
        const int k0 = kt*64;
        #pragma unroll
        for (int s=0;s<2;s++) {
            int idx = tid + 256*s;
            int r = idx >> 4, c = (idx & 15) << 2;
            float4 mv = *(const float4*)(M + (size_t)(i0+r)*SEQ + k0 + c);
            Ms[r][c+0]=mv.x; Ms[r][c+1]=mv.y; Ms[r][c+2]=mv.z; Ms[r][c+3]=mv.w;
        }
        #pragma unroll
        for (int s=0;s<4;s++) {
            int idx = tid + 256*s;
            int r = idx >> 4, c = (idx & 15) << 2;
            float4 vv = *(const float4*)(Vc + (size_t)(k0+r)*HD + c);
            Vs[r][c+0]=vv.x; Vs[r][c+1]=vv.y; Vs[r][c+2]=vv.z; Vs[r][c+3]=vv.w;
        }
        __syncthreads();

        #pragma unroll
        for (int u=0;u<2;u++) {
            int row = ty*2 + u;
            float tmax = -INFINITY;
            #pragma unroll
            for (int v=0;v<4;v++) tmax = fmaxf(tmax, Ms[row][tx*4+v]);
            #pragma unroll
            for (int off=1; off<16; off<<=1)
                tmax = fmaxf(tmax, __shfl_xor_sync(0xffffffffu, tmax, off));
            float newm = fmaxf(mrow[u], tmax);
            float corr = __expf(mrow[u] - newm);
            mrow[u] = newm;
            float tsum = 0.f;
            #pragma unroll
            for (int v=0;v<4;v++) {
                float p = __expf(Ms[row][tx*4+v] - newm);
                Ms[row][tx*4+v] = p;
                tsum += p;
            }
            #pragma unroll
            for (int off=1; off<16; off<<=1)
                tsum += __shfl_xor_sync(0xffffffffu, tsum, off);
            lrow[u] = lrow[u]*corr + tsum;
            #pragma unroll
            for (int v=0;v<4;v++) acc[u][v] *= corr;
        }
        __syncthreads();

        #pragma unroll 8
        for (int kk=0; kk<64; kk++) {
            float af[2], bf[4];
            #pragma unroll
            for (int u=0;u<2;u++) af[u] = Ms[ty*2+u][kk];
            #pragma unroll
            for (int v=0;v<4;v++) bf[v] = Vs[kk][tx*4+v];
            #pragma unroll
            for (int u=0;u<2;u++)
                #pragma unroll
                for (int v=0;v<4;v++) acc[u][v] = fmaf(af[u], bf[v], acc[u][v]);
        }
        __syncthreads();
    }

    #pragma unroll
    for (int u=0;u<2;u++) {
        int row = i0 + ty*2 + u;
        float inv = 1.f / lrow[u];
        *(float4*)(out + ((size_t)b*SEQ + row)*HD + tx*4) =
            make_float4(acc[u][0]*inv, acc[u][1]*inv, acc[u][2]*inv, acc[u][3]*inv);
    }
}

// ---------------------------------------------------------------------------
extern "C" void kernel_launch(void* const* d_in, const int* in_sizes, int n_in,
                              void* d_out, int out_size)
{
    (void)in_sizes; (void)n_in; (void)out_size;
    const float* x    = (const float*)d_in[0];
    const float* wqu  = (const float*)d_in[1];
    const float* wku  = (const float*)d_in[2];
    const float* wvu  = (const float*)d_in[3];
    const float* wqc  = (const float*)d_in[4];
    const float* wkc  = (const float*)d_in[5];
    const float* wvc  = (const float*)d_in[6];
    float* out = (float*)d_out;

    cudaFuncSetAttribute(su_mma_kernel, cudaFuncAttributeMaxDynamicSharedMemorySize, SU_SM_TOT);

    proj_kernel<<<dim3(128, 6), 256>>>(x, wqu, wku, wvu, wqc, wkc, wvc);
    ts_kernel<<<dim3(32, 32, 8), 256>>>();
    su_mma_kernel<<<dim3(136, 4), 256, SU_SM_TOT>>>();
    softpv_kernel<<<dim3(64, 4), 256>>>(out);
}